// round 7
// baseline (speedup 1.0000x reference)
#include <cuda_runtime.h>
#include <cuda_bf16.h>
#include <cstdint>

// Problem constants
#define BB   2
#define TT   4096
#define CC   768
#define HH   12
#define DH   64
#define BT   (BB*TT)          // 8192

// Scratch (device globals; allocation-free rule)
__device__ float g_q[BB*HH*TT*DH];   // [b*H+h][t][d]
__device__ float g_k[BB*HH*TT*DH];
__device__ float g_v[BB*HH*TT*DH];
__device__ float g_y[BT*CC];         // [b*T+t][c]

// ---------------------------------------------------------------------------
// Fast exp on the FMA pipe (no MUFU). |rel err| < 2e-6 for x <= 0.
// ---------------------------------------------------------------------------
__device__ __forceinline__ float fexp(float x) {
    float y = fmaxf(x * 1.4426950408889634f, -126.0f);
    float t = y + 12582912.0f;            // 2^23 + 2^22 : round-to-nearest-int
    int   i = __float_as_int(t);
    float f = y - (t - 12582912.0f);      // f in [-0.5, 0.5]
    float p =             1.3333558146e-3f;
    p = fmaf(p, f, 9.6181291076e-3f);
    p = fmaf(p, f, 5.5504108664e-2f);
    p = fmaf(p, f, 2.4022650696e-1f);
    p = fmaf(p, f, 6.9314718056e-1f);
    p = fmaf(p, f, 1.0f);
    return __int_as_float(__float_as_int(p) + (i << 23));
}

// ---------------------------------------------------------------------------
// tf32 mma.sync helpers.
// A frag: a0=(g, tg) a1=(g+8, tg) a2=(g, tg+4) a3=(g+8, tg+4)   [m, k]
// B frag: b0=(k=tg, n=g) b1=(k=tg+4, n=g)
// C frag: c0=(g, 2tg) c1=(g, 2tg+1) c2=(g+8, 2tg) c3=(g+8, 2tg+1)
//   g = lane/4, tg = lane%4.
// ---------------------------------------------------------------------------
#define MMA_TF32(c, a, b) \
    asm volatile("mma.sync.aligned.m16n8k8.row.col.f32.tf32.tf32.f32 " \
                 "{%0,%1,%2,%3}, {%4,%5,%6,%7}, {%8,%9}, {%0,%1,%2,%3};" \
                 : "+f"((c)[0]), "+f"((c)[1]), "+f"((c)[2]), "+f"((c)[3]) \
                 : "r"((a)[0]), "r"((a)[1]), "r"((a)[2]), "r"((a)[3]), \
                   "r"((b)[0]), "r"((b)[1]))

__device__ __forceinline__ uint32_t to_tf32(float v) {
    uint32_t u;
    asm("cvt.rna.tf32.f32 %0, %1;" : "=r"(u) : "f"(v));
    return u;
}

// Fragment-order scatter for GEMM kernels
__device__ __forceinline__ void scatterA(uint32_t* buf, int row, int c4, float4 v) {
    const int mt = row >> 4, rl = row & 15;
    float vv[4] = {v.x, v.y, v.z, v.w};
#pragma unroll
    for (int e = 0; e < 4; e++) {
        int c  = c4 * 4 + e;
        int ks = c >> 3, cl = c & 7;
        int t  = (rl & 7) * 4 + (cl & 3);
        int rg = (rl >> 3) + 2 * (cl >> 2);
        buf[((ks * 8 + mt) * 32 + t) * 4 + rg] = to_tf32(vv[e]);
    }
}

__device__ __forceinline__ void scatterB(uint32_t* buf, int n, int c4, float4 v) {
    const int nt = n >> 3, nl = n & 7;
    float vv[4] = {v.x, v.y, v.z, v.w};
#pragma unroll
    for (int e = 0; e < 4; e++) {
        int c  = c4 * 4 + e;
        int ks = c >> 3, kl = c & 7;
        int t  = nl * 4 + (kl & 3);
        int rg = kl >> 2;
        buf[((ks * 16 + nt) * 32 + t) * 2 + rg] = to_tf32(vv[e]);
    }
}

// ---------------------------------------------------------------------------
// tf32 GEMM (NT): out[r,c] = sum_k A[r,k]*W[c,k]. BM=128 BN=128 BK=16.
// ---------------------------------------------------------------------------
__device__ __forceinline__ void gemm_mma_loop(
    const float* __restrict__ Ab, const float* __restrict__ Bb,
    uint32_t sA[2][2048], uint32_t sB[2][2048],
    float c[4][4][4], int tid)
{
    const int lane   = tid & 31;
    const int wid    = tid >> 5;
    const int warp_m = wid >> 2;
    const int warp_n = wid & 3;

    const int rowA = tid >> 2;
    const int c4   = tid & 3;
    const float* pA0 = Ab + (size_t)rowA * CC + c4 * 4;
    const float* pA1 = pA0 + (size_t)64 * CC;
    const float* pB0 = Bb + (size_t)rowA * CC + c4 * 4;
    const float* pB1 = pB0 + (size_t)64 * CC;

#pragma unroll
    for (int im = 0; im < 4; im++)
#pragma unroll
        for (int in = 0; in < 4; in++)
#pragma unroll
            for (int k = 0; k < 4; k++) c[im][in][k] = 0.0f;

    {
        float4 a0 = *(const float4*)pA0;
        float4 a1 = *(const float4*)pA1;
        float4 b0 = *(const float4*)pB0;
        float4 b1 = *(const float4*)pB1;
        scatterA(sA[0], rowA, c4, a0);
        scatterA(sA[0], rowA + 64, c4, a1);
        scatterB(sB[0], rowA, c4, b0);
        scatterB(sB[0], rowA + 64, c4, b1);
    }
    __syncthreads();

    const int NK = CC / 16;   // 48
    for (int kc = 0; kc < NK; kc++) {
        const int s = kc & 1;
        float4 a0, a1, b0, b1;
        if (kc + 1 < NK) {
            const float* q = pA0 + (kc + 1) * 16;
            a0 = *(const float4*)q;
            a1 = *(const float4*)(q + (size_t)64 * CC);
            const float* r = pB0 + (kc + 1) * 16;
            b0 = *(const float4*)r;
            b1 = *(const float4*)(r + (size_t)64 * CC);
        }

#pragma unroll
        for (int ks = 0; ks < 2; ks++) {
            uint32_t af[4][4], bf[4][2];
#pragma unroll
            for (int im = 0; im < 4; im++) {
                const uint32_t* p = &sA[s][((ks * 8 + warp_m * 4 + im) * 32 + lane) * 4];
                uint4 v = *(const uint4*)p;
                af[im][0] = v.x; af[im][1] = v.y; af[im][2] = v.z; af[im][3] = v.w;
            }
#pragma unroll
            for (int in = 0; in < 4; in++) {
                const uint32_t* p = &sB[s][((ks * 16 + warp_n * 4 + in) * 32 + lane) * 2];
                uint2 v = *(const uint2*)p;
                bf[in][0] = v.x; bf[in][1] = v.y;
            }
#pragma unroll
            for (int im = 0; im < 4; im++)
#pragma unroll
                for (int in = 0; in < 4; in++)
                    MMA_TF32(c[im][in], af[im], bf[in]);
        }

        if (kc + 1 < NK) {
            uint32_t* dA = sA[s ^ 1];
            uint32_t* dB = sB[s ^ 1];
            scatterA(dA, rowA, c4, a0);
            scatterA(dA, rowA + 64, c4, a1);
            scatterB(dB, rowA, c4, b0);
            scatterB(dB, rowA + 64, c4, b1);
        }
        __syncthreads();
    }
}

__global__ void __launch_bounds__(256) qkv_mma_kernel(
    const float* __restrict__ X,
    const float* __restrict__ Wq_,
    const float* __restrict__ Wk_,
    const float* __restrict__ Wv_)
{
    __shared__ uint32_t sA[2][2048];
    __shared__ uint32_t sB[2][2048];

    const int z  = blockIdx.z;
    const float* W = (z == 0) ? Wq_ : (z == 1) ? Wk_ : Wv_;
    float* dst     = (z == 0) ? g_q : (z == 1) ? g_k : g_v;

    const int cb  = blockIdx.x;
    const int rb  = blockIdx.y;
    const int tid = threadIdx.x;

    float c[4][4][4];
    gemm_mma_loop(X + (size_t)rb * 128 * CC, W + (size_t)cb * 128 * CC,
                  sA, sB, c, tid);

    const int lane   = tid & 31;
    const int wid    = tid >> 5;
    const int warp_m = wid >> 2;
    const int warp_n = wid & 3;
    const int g  = lane >> 2;
    const int tg = lane & 3;

#pragma unroll
    for (int im = 0; im < 4; im++) {
        int r0 = rb * 128 + warp_m * 64 + im * 16 + g;
#pragma unroll
        for (int in = 0; in < 4; in++) {
            int colb = warp_n * 32 + in * 8 + 2 * tg;
            int hp   = colb >> 6;
            int d    = colb & 63;
            {
                int b = r0 >> 12, t = r0 & (TT - 1);
                float* p = dst + ((size_t)(b * HH + cb * 2 + hp) * TT + t) * DH + d;
                *(float2*)p = make_float2(c[im][in][0], c[im][in][1]);
            }
            {
                int r1 = r0 + 8;
                int b = r1 >> 12, t = r1 & (TT - 1);
                float* p = dst + ((size_t)(b * HH + cb * 2 + hp) * TT + t) * DH + d;
                *(float2*)p = make_float2(c[im][in][2], c[im][in][3]);
            }
        }
    }
}

__global__ void __launch_bounds__(256) proj_mma_kernel(
    const float* __restrict__ Wp,
    const float* __restrict__ bp,
    float* __restrict__ out)
{
    __shared__ uint32_t sA[2][2048];
    __shared__ uint32_t sB[2][2048];

    const int cb  = blockIdx.x;
    const int rb  = blockIdx.y;
    const int tid = threadIdx.x;

    float c[4][4][4];
    gemm_mma_loop(g_y + (size_t)rb * 128 * CC, Wp + (size_t)cb * 128 * CC,
                  sA, sB, c, tid);

    const int lane   = tid & 31;
    const int wid    = tid >> 5;
    const int warp_m = wid >> 2;
    const int warp_n = wid & 3;
    const int g  = lane >> 2;
    const int tg = lane & 3;

#pragma unroll
    for (int im = 0; im < 4; im++) {
        int r0 = rb * 128 + warp_m * 64 + im * 16 + g;
#pragma unroll
        for (int in = 0; in < 4; in++) {
            int colb = warp_n * 32 + in * 8 + 2 * tg;
            int col  = cb * 128 + colb;
            float b0 = bp[col], b1 = bp[col + 1];
            *(float2*)(out + (size_t)r0 * CC + col) =
                make_float2(c[im][in][0] + b0, c[im][in][1] + b1);
            *(float2*)(out + (size_t)(r0 + 8) * CC + col) =
                make_float2(c[im][in][2] + b0, c[im][in][3] + b1);
        }
    }
}

// ---------------------------------------------------------------------------
// Flash attention on tensor pipe (tf32 mma, fp32 accum, causal).
// 256 threads = 8 warps; warp w owns query rows qt*128 + w*16 + [0,16).
// K/V double-buffered via register prefetch (LDG overlaps compute).
// Q fragments live in smem (A-frag order, per warp): 1 LDS.128 per ks.
// smem (96KB dynamic, u32):
//   sK [4096]  : K tile 64x64, B-frag order for S   (n=j, k=d)
//   sV [4096]  : V tile 64x64, B-frag order for PV  (n=d, k=j)
//   sQ [8192]  : per-warp 1024: Q 16x64 in A-frag order
//   sP [8192]  : per-warp 1024: P 16x64 in A-frag order
// ---------------------------------------------------------------------------
__global__ void __launch_bounds__(256, 2) attn_mma_kernel()
{
    extern __shared__ uint32_t smem_u[];
    uint32_t* sK = smem_u;             // 4096
    uint32_t* sV = smem_u + 4096;      // 4096
    uint32_t* sQ = smem_u + 8192;      // 8192
    uint32_t* sP = smem_u + 16384;     // 8192

    const int qt = (gridDim.x - 1) - blockIdx.x;   // heavy tiles first
    const int bh = blockIdx.y;
    const float* qb = g_q + (size_t)bh * TT * DH;
    const float* kb = g_k + (size_t)bh * TT * DH;
    const float* vb = g_v + (size_t)bh * TT * DH;

    const int tid  = threadIdx.x;
    const int w    = tid >> 5;
    const int lane = tid & 31;
    const int g    = lane >> 2;
    const int tg   = lane & 3;

    // ---- Stage Q tile (128x64, pre-scaled, tf32) directly into A-frag smem
#pragma unroll
    for (int l = 0; l < 8; l++) {
        int idx = l * 256 + tid;          // 0..2047 float4s
        int i  = idx >> 4;                // row 0..127
        int f4 = idx & 15;                // float4 within row
        float4 v = *(const float4*)(qb + (size_t)(qt * 128 + i) * DH + f4 * 4);
        const int wi = i >> 4, rl = i & 15;
        const int ks = f4 >> 1;
        const int rg = (rl >> 3) + 2 * (f4 & 1);
        const int t0 = (rl & 7) * 4;
        uint32_t* dst = sQ + wi * 1024 + (ks * 32 + t0) * 4 + rg;
        dst[0]  = to_tf32(v.x * 0.125f);
        dst[4]  = to_tf32(v.y * 0.125f);
        dst[8]  = to_tf32(v.z * 0.125f);
        dst[12] = to_tf32(v.w * 0.125f);
    }

    float o[8][4];
#pragma unroll
    for (int nt = 0; nt < 8; nt++)
#pragma unroll
        for (int k = 0; k < 4; k++) o[nt][k] = 0.0f;
    float mrowA = -1e30f, mrowB = -1e30f, lrowA = 0.0f, lrowB = 0.0f;

    uint32_t* Pw = sP + w * 1024;
    const uint32_t* Qw = sQ + w * 1024;
    const int iA = qt * 128 + w * 16 + g;
    const int iB = iA + 8;

    const int ktiles = 2 * qt + 2;

    // ---- prefetch k-tile 0 into registers
    float4 kreg[4], vreg[4];
#pragma unroll
    for (int l = 0; l < 4; l++) {
        int idx = l * 256 + tid;
        int j  = idx >> 4;
        int f4 = idx & 15;
        kreg[l] = *(const float4*)(kb + (size_t)j * DH + f4 * 4);
        vreg[l] = *(const float4*)(vb + (size_t)j * DH + f4 * 4);
    }

    for (int kt = 0; kt < ktiles; kt++) {
        // ---- scatter prefetched K/V registers into fragment-ordered smem
#pragma unroll
        for (int l = 0; l < 4; l++) {
            int idx = l * 256 + tid;
            int j  = idx >> 4;
            int f4 = idx & 15;
            // K: ks=d>>3=f4>>1, nt=j>>3, t=(j&7)*4+e, rg=f4&1
            {
                const int base = (((f4 >> 1) * 8 + (j >> 3)) * 32 + (j & 7) * 4) * 2 + (f4 & 1);
                float kk[4] = {kreg[l].x, kreg[l].y, kreg[l].z, kreg[l].w};
#pragma unroll
                for (int e = 0; e < 4; e++)
                    sK[base + e * 2] = to_tf32(kk[e]);
            }
            // V: ks=j>>3, nt=f4>>1, t=(4*(f4&1)+e)*4+(j&3), rg=(j>>2)&1
            {
                const int base = (((j >> 3) * 8 + (f4 >> 1)) * 32 + (f4 & 1) * 16 + (j & 3)) * 2
                                 + ((j >> 2) & 1);
                float vv[4] = {vreg[l].x, vreg[l].y, vreg[l].z, vreg[l].w};
#pragma unroll
                for (int e = 0; e < 4; e++)
                    sV[base + e * 8] = to_tf32(vv[e]);
            }
        }
        __syncthreads();   // scatter visible; Q staging done (iter 0)

        // ---- prefetch next tile (LDG latency overlaps compute below)
        if (kt + 1 < ktiles) {
            const float* kp = kb + (size_t)(kt + 1) * 64 * DH;
            const float* vp = vb + (size_t)(kt + 1) * 64 * DH;
#pragma unroll
            for (int l = 0; l < 4; l++) {
                int idx = l * 256 + tid;
                int j  = idx >> 4;
                int f4 = idx & 15;
                kreg[l] = *(const float4*)(kp + (size_t)j * DH + f4 * 4);
                vreg[l] = *(const float4*)(vp + (size_t)j * DH + f4 * 4);
            }
        }

        // ---- S = Q K^T (16x64 per warp)
        float s[8][4];
#pragma unroll
        for (int nt = 0; nt < 8; nt++)
#pragma unroll
            for (int k = 0; k < 4; k++) s[nt][k] = 0.0f;

#pragma unroll
        for (int ks = 0; ks < 8; ks++) {
            uint4 qv = *(const uint4*)&Qw[(ks * 32 + lane) * 4];
            uint32_t qa[4] = {qv.x, qv.y, qv.z, qv.w};
#pragma unroll
            for (int nt = 0; nt < 8; nt++) {
                uint2 bv = *(const uint2*)&sK[((ks * 8 + nt) * 32 + lane) * 2];
                uint32_t bf[2] = {bv.x, bv.y};
                MMA_TF32(s[nt], qa, bf);
            }
        }

        // ---- causal mask (only last two k-tiles touch the diagonal)
        if (kt >= 2 * qt) {
#pragma unroll
            for (int nt = 0; nt < 8; nt++) {
                int j0 = kt * 64 + nt * 8 + 2 * tg;
                if (j0     > iA) s[nt][0] = -1e30f;
                if (j0 + 1 > iA) s[nt][1] = -1e30f;
                if (j0     > iB) s[nt][2] = -1e30f;
                if (j0 + 1 > iB) s[nt][3] = -1e30f;
            }
        }

        // ---- online softmax (2 rows per thread, quad reduction)
        float mA = s[0][0], mB = s[0][2];
#pragma unroll
        for (int nt = 0; nt < 8; nt++) {
            mA = fmaxf(mA, fmaxf(s[nt][0], s[nt][1]));
            mB = fmaxf(mB, fmaxf(s[nt][2], s[nt][3]));
        }
        mA = fmaxf(mA, __shfl_xor_sync(0xffffffffu, mA, 1));
        mA = fmaxf(mA, __shfl_xor_sync(0xffffffffu, mA, 2));
        mB = fmaxf(mB, __shfl_xor_sync(0xffffffffu, mB, 1));
        mB = fmaxf(mB, __shfl_xor_sync(0xffffffffu, mB, 2));
        float mnA = fmaxf(mrowA, mA), mnB = fmaxf(mrowB, mB);
        float aA  = fexp(mrowA - mnA), aB = fexp(mrowB - mnB);
        mrowA = mnA; mrowB = mnB;

        float rsA = 0.0f, rsB = 0.0f;
#pragma unroll
        for (int nt = 0; nt < 8; nt++) {
            s[nt][0] = fexp(s[nt][0] - mnA);
            s[nt][1] = fexp(s[nt][1] - mnA);
            s[nt][2] = fexp(s[nt][2] - mnB);
            s[nt][3] = fexp(s[nt][3] - mnB);
            rsA += s[nt][0] + s[nt][1];
            rsB += s[nt][2] + s[nt][3];
        }
        rsA += __shfl_xor_sync(0xffffffffu, rsA, 1);
        rsA += __shfl_xor_sync(0xffffffffu, rsA, 2);
        rsB += __shfl_xor_sync(0xffffffffu, rsB, 1);
        rsB += __shfl_xor_sync(0xffffffffu, rsB, 2);
        lrowA = lrowA * aA + rsA;
        lrowB = lrowB * aB + rsB;
#pragma unroll
        for (int nt = 0; nt < 8; nt++) {
            o[nt][0] *= aA; o[nt][1] *= aA;
            o[nt][2] *= aB; o[nt][3] *= aB;
        }

        // ---- stage P (tf32) to warp-private smem in A-frag order
        {
            const int t0  = g * 4 + ((2 * tg) & 3);
            const int rg0 = 2 * (tg >> 1);
#pragma unroll
            for (int nt = 0; nt < 8; nt++) {
                uint32_t p00 = to_tf32(s[nt][0]);
                uint32_t p10 = to_tf32(s[nt][2]);
                uint32_t p01 = to_tf32(s[nt][1]);
                uint32_t p11 = to_tf32(s[nt][3]);
                *(uint2*)&Pw[(nt * 32 + t0) * 4 + rg0]     = make_uint2(p00, p10);
                *(uint2*)&Pw[(nt * 32 + t0 + 1) * 4 + rg0] = make_uint2(p01, p11);
            }
        }
        __syncwarp();

        // ---- O += P V (16x64 per warp)
#pragma unroll
        for (int ks = 0; ks < 8; ks++) {
            uint4 av = *(const uint4*)&Pw[(ks * 32 + lane) * 4];
            uint32_t af[4] = {av.x, av.y, av.z, av.w};
#pragma unroll
            for (int nt = 0; nt < 8; nt++) {
                uint2 bv = *(const uint2*)&sV[((ks * 8 + nt) * 32 + lane) * 2];
                uint32_t bf[2] = {bv.x, bv.y};
                MMA_TF32(o[nt], af, bf);
            }
        }
        __syncthreads();   // all warps done reading sK/sV before next scatter
    }

    // ---- finalize: g_y[b*T+t][h*64+d]
    const int b = bh / HH;
    const int h = bh % HH;
    const float invA = 1.0f / lrowA;
    const float invB = 1.0f / lrowB;
    float* rowA = g_y + (size_t)(b * TT + iA) * CC + h * DH;
    float* rowB = g_y + (size_t)(b * TT + iB) * CC + h * DH;
#pragma unroll
    for (int nt = 0; nt < 8; nt++) {
        int d = nt * 8 + 2 * tg;
        *(float2*)(rowA + d) = make_float2(o[nt][0] * invA, o[nt][1] * invA);
        *(float2*)(rowB + d) = make_float2(o[nt][2] * invB, o[nt][3] * invB);
    }
}

// ---------------------------------------------------------------------------

extern "C" void kernel_launch(void* const* d_in, const int* in_sizes, int n_in,
                              void* d_out, int out_size)
{
    const float* x  = (const float*)d_in[0];
    const float* Wk = (const float*)d_in[1];
    const float* Wq = (const float*)d_in[2];
    const float* Wv = (const float*)d_in[3];
    const float* Wp = (const float*)d_in[4];
    const float* bp = (const float*)d_in[5];
    float* out = (float*)d_out;

    const int attn_smem = 24576 * 4;   // 96KB
    cudaFuncSetAttribute(attn_mma_kernel,
                         cudaFuncAttributeMaxDynamicSharedMemorySize, attn_smem);

    // QKV projections (tf32 mma.sync)
    qkv_mma_kernel<<<dim3(6, 64, 3), 256>>>(x, Wq, Wk, Wv);

    // Flash attention on tensor pipe, K/V register-prefetch pipelined
    attn_mma_kernel<<<dim3(32, 24), 256, attn_smem>>>();

    // Output projection + bias (tf32 mma.sync)
    proj_mma_kernel<<<dim3(6, 64), 256>>>(Wp, bp, out);
}

// round 8
// speedup vs baseline: 1.4524x; 1.4524x over previous
#include <cuda_runtime.h>
#include <cuda_bf16.h>
#include <cstdint>

// Problem constants
#define BB   2
#define TT   4096
#define CC   768
#define HH   12
#define DH   64
#define BT   (BB*TT)          // 8192

// Scratch (device globals; allocation-free rule).
// g_q: tf32 A-frag order  [bh][t/16][ks=d/8][lane*4+rg]          (128 u32 per ks)
// g_k: tf32 B-frag order  [bh][kt=t/64][ ((d/8)*8+(jl/8))*32 + (jl&7)*4+(d&3) ]*2 + ((d>>2)&1)
// g_v: tf32 B-frag order  [bh][kt]     [ ((jl/8)*8+(d/8))*32 + (d&7)*4+(jl&3) ]*2 + ((jl>>2)&1)
__device__ __align__(128) uint32_t g_q[BB*HH*TT*DH];
__device__ __align__(128) uint32_t g_k[BB*HH*TT*DH];
__device__ __align__(128) uint32_t g_v[BB*HH*TT*DH];
__device__ float g_y[BT*CC];         // [b*T+t][c]

// ---------------------------------------------------------------------------
// Fast exp on the FMA pipe (no MUFU). |rel err| < 2e-6 for x <= 0.
// ---------------------------------------------------------------------------
__device__ __forceinline__ float fexp(float x) {
    float y = fmaxf(x * 1.4426950408889634f, -126.0f);
    float t = y + 12582912.0f;
    int   i = __float_as_int(t);
    float f = y - (t - 12582912.0f);
    float p =             1.3333558146e-3f;
    p = fmaf(p, f, 9.6181291076e-3f);
    p = fmaf(p, f, 5.5504108664e-2f);
    p = fmaf(p, f, 2.4022650696e-1f);
    p = fmaf(p, f, 6.9314718056e-1f);
    p = fmaf(p, f, 1.0f);
    return __int_as_float(__float_as_int(p) + (i << 23));
}

// ---------------------------------------------------------------------------
// tf32 mma.sync helpers.
// A frag: a0=(g, tg) a1=(g+8, tg) a2=(g, tg+4) a3=(g+8, tg+4)   [m, k]
// B frag: b0=(k=tg, n=g) b1=(k=tg+4, n=g)
// C frag: c0=(g, 2tg) c1=(g, 2tg+1) c2=(g+8, 2tg) c3=(g+8, 2tg+1)
// ---------------------------------------------------------------------------
#define MMA_TF32(c, a, b) \
    asm volatile("mma.sync.aligned.m16n8k8.row.col.f32.tf32.tf32.f32 " \
                 "{%0,%1,%2,%3}, {%4,%5,%6,%7}, {%8,%9}, {%0,%1,%2,%3};" \
                 : "+f"((c)[0]), "+f"((c)[1]), "+f"((c)[2]), "+f"((c)[3]) \
                 : "r"((a)[0]), "r"((a)[1]), "r"((a)[2]), "r"((a)[3]), \
                   "r"((b)[0]), "r"((b)[1]))

__device__ __forceinline__ uint32_t to_tf32(float v) {
    uint32_t u;
    asm("cvt.rna.tf32.f32 %0, %1;" : "=r"(u) : "f"(v));
    return u;
}

__device__ __forceinline__ uint32_t smem_u32(const void* p) {
    uint32_t a;
    asm("{ .reg .u64 t; cvta.to.shared.u64 t, %1; cvt.u32.u64 %0, t; }"
        : "=r"(a) : "l"(p));
    return a;
}

#define CP_ASYNC16(dst, src) \
    asm volatile("cp.async.cg.shared.global [%0], [%1], 16;" \
                 :: "r"(dst), "l"(src) : "memory")
#define CP_COMMIT() asm volatile("cp.async.commit_group;" ::: "memory")
#define CP_WAIT0()  asm volatile("cp.async.wait_group 0;" ::: "memory")

// Fragment-order scatter for GEMM kernels
__device__ __forceinline__ void scatterA(uint32_t* buf, int row, int c4, float4 v) {
    const int mt = row >> 4, rl = row & 15;
    float vv[4] = {v.x, v.y, v.z, v.w};
#pragma unroll
    for (int e = 0; e < 4; e++) {
        int c  = c4 * 4 + e;
        int ks = c >> 3, cl = c & 7;
        int t  = (rl & 7) * 4 + (cl & 3);
        int rg = (rl >> 3) + 2 * (cl >> 2);
        buf[((ks * 8 + mt) * 32 + t) * 4 + rg] = to_tf32(vv[e]);
    }
}

__device__ __forceinline__ void scatterB(uint32_t* buf, int n, int c4, float4 v) {
    const int nt = n >> 3, nl = n & 7;
    float vv[4] = {v.x, v.y, v.z, v.w};
#pragma unroll
    for (int e = 0; e < 4; e++) {
        int c  = c4 * 4 + e;
        int ks = c >> 3, kl = c & 7;
        int t  = nl * 4 + (kl & 3);
        int rg = kl >> 2;
        buf[((ks * 16 + nt) * 32 + t) * 2 + rg] = to_tf32(vv[e]);
    }
}

// ---------------------------------------------------------------------------
// tf32 GEMM (NT): out[r,c] = sum_k A[r,k]*W[c,k]. BM=128 BN=128 BK=16.
// ---------------------------------------------------------------------------
__device__ __forceinline__ void gemm_mma_loop(
    const float* __restrict__ Ab, const float* __restrict__ Bb,
    uint32_t sA[2][2048], uint32_t sB[2][2048],
    float c[4][4][4], int tid)
{
    const int lane   = tid & 31;
    const int wid    = tid >> 5;
    const int warp_m = wid >> 2;
    const int warp_n = wid & 3;

    const int rowA = tid >> 2;
    const int c4   = tid & 3;
    const float* pA0 = Ab + (size_t)rowA * CC + c4 * 4;
    const float* pA1 = pA0 + (size_t)64 * CC;
    const float* pB0 = Bb + (size_t)rowA * CC + c4 * 4;
    const float* pB1 = pB0 + (size_t)64 * CC;

#pragma unroll
    for (int im = 0; im < 4; im++)
#pragma unroll
        for (int in = 0; in < 4; in++)
#pragma unroll
            for (int k = 0; k < 4; k++) c[im][in][k] = 0.0f;

    {
        float4 a0 = *(const float4*)pA0;
        float4 a1 = *(const float4*)pA1;
        float4 b0 = *(const float4*)pB0;
        float4 b1 = *(const float4*)pB1;
        scatterA(sA[0], rowA, c4, a0);
        scatterA(sA[0], rowA + 64, c4, a1);
        scatterB(sB[0], rowA, c4, b0);
        scatterB(sB[0], rowA + 64, c4, b1);
    }
    __syncthreads();

    const int NK = CC / 16;   // 48
    for (int kc = 0; kc < NK; kc++) {
        const int s = kc & 1;
        float4 a0, a1, b0, b1;
        if (kc + 1 < NK) {
            const float* q = pA0 + (kc + 1) * 16;
            a0 = *(const float4*)q;
            a1 = *(const float4*)(q + (size_t)64 * CC);
            const float* r = pB0 + (kc + 1) * 16;
            b0 = *(const float4*)r;
            b1 = *(const float4*)(r + (size_t)64 * CC);
        }

#pragma unroll
        for (int ks = 0; ks < 2; ks++) {
            uint32_t af[4][4], bf[4][2];
#pragma unroll
            for (int im = 0; im < 4; im++) {
                const uint32_t* p = &sA[s][((ks * 8 + warp_m * 4 + im) * 32 + lane) * 4];
                uint4 v = *(const uint4*)p;
                af[im][0] = v.x; af[im][1] = v.y; af[im][2] = v.z; af[im][3] = v.w;
            }
#pragma unroll
            for (int in = 0; in < 4; in++) {
                const uint32_t* p = &sB[s][((ks * 16 + warp_n * 4 + in) * 32 + lane) * 2];
                uint2 v = *(const uint2*)p;
                bf[in][0] = v.x; bf[in][1] = v.y;
            }
#pragma unroll
            for (int im = 0; im < 4; im++)
#pragma unroll
                for (int in = 0; in < 4; in++)
                    MMA_TF32(c[im][in], af[im], bf[in]);
        }

        if (kc + 1 < NK) {
            uint32_t* dA = sA[s ^ 1];
            uint32_t* dB = sB[s ^ 1];
            scatterA(dA, rowA, c4, a0);
            scatterA(dA, rowA + 64, c4, a1);
            scatterB(dB, rowA, c4, b0);
            scatterB(dB, rowA + 64, c4, b1);
        }
        __syncthreads();
    }
}

// ---------------------------------------------------------------------------
// QKV projection: epilogue writes tf32 FRAGMENT-ORDERED Q/K/V to gmem.
// ---------------------------------------------------------------------------
__global__ void __launch_bounds__(256) qkv_mma_kernel(
    const float* __restrict__ X,
    const float* __restrict__ Wq_,
    const float* __restrict__ Wk_,
    const float* __restrict__ Wv_)
{
    __shared__ uint32_t sA[2][2048];
    __shared__ uint32_t sB[2][2048];

    const int z  = blockIdx.z;
    const float* W = (z == 0) ? Wq_ : (z == 1) ? Wk_ : Wv_;

    const int cb  = blockIdx.x;    // 0..5 : 128 out-cols = 2 heads
    const int rb  = blockIdx.y;    // 0..63
    const int tid = threadIdx.x;

    float c[4][4][4];
    gemm_mma_loop(X + (size_t)rb * 128 * CC, W + (size_t)cb * 128 * CC,
                  sA, sB, c, tid);

    const int lane   = tid & 31;
    const int wid    = tid >> 5;
    const int warp_m = wid >> 2;
    const int warp_n = wid & 3;
    const int g  = lane >> 2;
    const int tg = lane & 3;

    if (z == 0) {
        // Q -> A-frag order, pre-scaled by 0.125
#pragma unroll
        for (int im = 0; im < 4; im++) {
            int r0 = rb * 128 + warp_m * 64 + im * 16 + g;
            int b  = r0 >> 12;
            int gw = (r0 >> 4) & 255;
#pragma unroll
            for (int in = 0; in < 4; in++) {
                int colb = warp_n * 32 + in * 8 + 2 * tg;
                int hp = colb >> 6, d = colb & 63;
                int bh = b * HH + cb * 2 + hp;
                size_t base = ((size_t)(bh * 256 + gw) * 8 + (d >> 3)) * 128;
                int tf  = g * 4 + (d & 3);
                int rgb = 2 * ((d >> 2) & 1);
                *(uint2*)&g_q[base + tf * 4 + rgb] =
                    make_uint2(to_tf32(c[im][in][0] * 0.125f),
                               to_tf32(c[im][in][2] * 0.125f));
                *(uint2*)&g_q[base + (tf + 1) * 4 + rgb] =
                    make_uint2(to_tf32(c[im][in][1] * 0.125f),
                               to_tf32(c[im][in][3] * 0.125f));
            }
        }
    } else if (z == 1) {
        // K -> B-frag order (n=token, k=dim)
#pragma unroll
        for (int im = 0; im < 4; im++) {
#pragma unroll
            for (int rp = 0; rp < 2; rp++) {
                int r  = rb * 128 + warp_m * 64 + im * 16 + g + rp * 8;
                int b  = r >> 12;
                int t  = r & 4095;
                int jt = t >> 6, jl = t & 63;
#pragma unroll
                for (int in = 0; in < 4; in++) {
                    int colb = warp_n * 32 + in * 8 + 2 * tg;
                    int hp = colb >> 6, d = colb & 63;
                    int bh = b * HH + cb * 2 + hp;
                    size_t base = (size_t)(bh * 64 + jt) * 4096;
                    int idx = (((d >> 3) * 8 + (jl >> 3)) * 32 +
                               ((jl & 7) * 4 + (d & 3))) * 2 + ((d >> 2) & 1);
                    g_k[base + idx]     = to_tf32(c[im][in][rp ? 2 : 0]);
                    g_k[base + idx + 2] = to_tf32(c[im][in][rp ? 3 : 1]);
                }
            }
        }
    } else {
        // V -> B-frag order (n=dim, k=token)
#pragma unroll
        for (int im = 0; im < 4; im++) {
#pragma unroll
            for (int rp = 0; rp < 2; rp++) {
                int r  = rb * 128 + warp_m * 64 + im * 16 + g + rp * 8;
                int b  = r >> 12;
                int t  = r & 4095;
                int jt = t >> 6, jl = t & 63;
#pragma unroll
                for (int in = 0; in < 4; in++) {
                    int colb = warp_n * 32 + in * 8 + 2 * tg;
                    int hp = colb >> 6, d = colb & 63;
                    int bh = b * HH + cb * 2 + hp;
                    size_t base = (size_t)(bh * 64 + jt) * 4096;
                    int idx = (((jl >> 3) * 8 + (d >> 3)) * 32 +
                               ((d & 7) * 4 + (jl & 3))) * 2 + ((jl >> 2) & 1);
                    g_v[base + idx]     = to_tf32(c[im][in][rp ? 2 : 0]);
                    g_v[base + idx + 8] = to_tf32(c[im][in][rp ? 3 : 1]);
                }
            }
        }
    }
}

__global__ void __launch_bounds__(256) proj_mma_kernel(
    const float* __restrict__ Wp,
    const float* __restrict__ bp,
    float* __restrict__ out)
{
    __shared__ uint32_t sA[2][2048];
    __shared__ uint32_t sB[2][2048];

    const int cb  = blockIdx.x;
    const int rb  = blockIdx.y;
    const int tid = threadIdx.x;

    float c[4][4][4];
    gemm_mma_loop(g_y + (size_t)rb * 128 * CC, Wp + (size_t)cb * 128 * CC,
                  sA, sB, c, tid);

    const int lane   = tid & 31;
    const int wid    = tid >> 5;
    const int warp_m = wid >> 2;
    const int warp_n = wid & 3;
    const int g  = lane >> 2;
    const int tg = lane & 3;

#pragma unroll
    for (int im = 0; im < 4; im++) {
        int r0 = rb * 128 + warp_m * 64 + im * 16 + g;
#pragma unroll
        for (int in = 0; in < 4; in++) {
            int colb = warp_n * 32 + in * 8 + 2 * tg;
            int col  = cb * 128 + colb;
            float b0 = bp[col], b1 = bp[col + 1];
            *(float2*)(out + (size_t)r0 * CC + col) =
                make_float2(c[im][in][0] + b0, c[im][in][1] + b1);
            *(float2*)(out + (size_t)(r0 + 8) * CC + col) =
                make_float2(c[im][in][2] + b0, c[im][in][3] + b1);
        }
    }
}

// ---------------------------------------------------------------------------
// Flash attention, tensor pipe, pre-fragmented gmem K/V + cp.async double
// buffering (1 barrier per k-tile). Q fragments in registers.
// smem (96KB): sK[2][4096] | sV[2][4096] | sP[8][1024]   (u32)
// ---------------------------------------------------------------------------
__global__ void __launch_bounds__(256, 2) attn_mma_kernel()
{
    extern __shared__ uint32_t smem_u[];
    uint32_t* sK = smem_u;             // 2 x 4096
    uint32_t* sV = smem_u + 8192;      // 2 x 4096
    uint32_t* sP = smem_u + 16384;     // 8 x 1024
    const uint32_t sbase = smem_u32(smem_u);

    const int qt = (gridDim.x - 1) - blockIdx.x;   // heavy tiles first
    const int bh = blockIdx.y;

    const int tid  = threadIdx.x;
    const int w    = tid >> 5;
    const int lane = tid & 31;
    const int g    = lane >> 2;
    const int tg   = lane & 3;

    // ---- Q fragments (already tf32, scaled, A-frag order in gmem)
    uint32_t qa[8][4];
    {
        const uint32_t* qbase = g_q + ((size_t)(bh * 256 + qt * 8 + w) * 8) * 128 + lane * 4;
#pragma unroll
        for (int ks = 0; ks < 8; ks++) {
            uint4 v = *(const uint4*)(qbase + ks * 128);
            qa[ks][0] = v.x; qa[ks][1] = v.y; qa[ks][2] = v.z; qa[ks][3] = v.w;
        }
    }

    float o[8][4];
#pragma unroll
    for (int nt = 0; nt < 8; nt++)
#pragma unroll
        for (int k = 0; k < 4; k++) o[nt][k] = 0.0f;
    float mrowA = -1e30f, mrowB = -1e30f, lrowA = 0.0f, lrowB = 0.0f;

    uint32_t* Pw = sP + w * 1024;
    const int iA = qt * 128 + w * 16 + g;
    const int iB = iA + 8;

    const int ktiles = 2 * qt + 2;
    const uint32_t* kgb = g_k + (size_t)bh * 64 * 4096;
    const uint32_t* vgb = g_v + (size_t)bh * 64 * 4096;

    // issue: copy 16KB K + 16KB V of tile kt into buffer s
    auto issue_tile = [&](int kt, int s) {
        const uint32_t* kg = kgb + (size_t)kt * 4096 + tid * 4;
        const uint32_t* vg = vgb + (size_t)kt * 4096 + tid * 4;
        uint32_t kd = sbase + s * 16384 + tid * 16;
        uint32_t vd = sbase + 32768 + s * 16384 + tid * 16;
#pragma unroll
        for (int p = 0; p < 4; p++) {
            CP_ASYNC16(kd + p * 4096, kg + p * 1024);
            CP_ASYNC16(vd + p * 4096, vg + p * 1024);
        }
    };

    issue_tile(0, 0);
    CP_COMMIT();

    for (int kt = 0; kt < ktiles; kt++) {
        const int s = kt & 1;
        CP_WAIT0();          // tile kt landed (issued a full iteration ago)
        __syncthreads();     // visible to all; all warps done with tile kt-1

        if (kt + 1 < ktiles) {
            issue_tile(kt + 1, s ^ 1);   // overwrites buffer of tile kt-1 (safe)
            CP_COMMIT();
        }

        const uint32_t* sKs = sK + s * 4096;
        const uint32_t* sVs = sV + s * 4096;

        // ---- S = Q K^T (16x64 per warp)
        float sfr[8][4];
#pragma unroll
        for (int nt = 0; nt < 8; nt++)
#pragma unroll
            for (int k = 0; k < 4; k++) sfr[nt][k] = 0.0f;

#pragma unroll
        for (int ks = 0; ks < 8; ks++) {
#pragma unroll
            for (int nt = 0; nt < 8; nt++) {
                uint2 bv = *(const uint2*)&sKs[((ks * 8 + nt) * 32 + lane) * 2];
                uint32_t bf[2] = {bv.x, bv.y};
                MMA_TF32(sfr[nt], qa[ks], bf);
            }
        }

        // ---- causal mask
        if (kt >= 2 * qt) {
#pragma unroll
            for (int nt = 0; nt < 8; nt++) {
                int j0 = kt * 64 + nt * 8 + 2 * tg;
                if (j0     > iA) sfr[nt][0] = -1e30f;
                if (j0 + 1 > iA) sfr[nt][1] = -1e30f;
                if (j0     > iB) sfr[nt][2] = -1e30f;
                if (j0 + 1 > iB) sfr[nt][3] = -1e30f;
            }
        }

        // ---- online softmax (2 rows per thread, quad reduction)
        float mA = sfr[0][0], mB = sfr[0][2];
#pragma unroll
        for (int nt = 0; nt < 8; nt++) {
            mA = fmaxf(mA, fmaxf(sfr[nt][0], sfr[nt][1]));
            mB = fmaxf(mB, fmaxf(sfr[nt][2], sfr[nt][3]));
        }
        mA = fmaxf(mA, __shfl_xor_sync(0xffffffffu, mA, 1));
        mA = fmaxf(mA, __shfl_xor_sync(0xffffffffu, mA, 2));
        mB = fmaxf(mB, __shfl_xor_sync(0xffffffffu, mB, 1));
        mB = fmaxf(mB, __shfl_xor_sync(0xffffffffu, mB, 2));
        float mnA = fmaxf(mrowA, mA), mnB = fmaxf(mrowB, mB);
        float aA  = fexp(mrowA - mnA), aB = fexp(mrowB - mnB);
        mrowA = mnA; mrowB = mnB;

        float rsA = 0.0f, rsB = 0.0f;
#pragma unroll
        for (int nt = 0; nt < 8; nt++) {
            sfr[nt][0] = fexp(sfr[nt][0] - mnA);
            sfr[nt][1] = fexp(sfr[nt][1] - mnA);
            sfr[nt][2] = fexp(sfr[nt][2] - mnB);
            sfr[nt][3] = fexp(sfr[nt][3] - mnB);
            rsA += sfr[nt][0] + sfr[nt][1];
            rsB += sfr[nt][2] + sfr[nt][3];
        }
        rsA += __shfl_xor_sync(0xffffffffu, rsA, 1);
        rsA += __shfl_xor_sync(0xffffffffu, rsA, 2);
        rsB += __shfl_xor_sync(0xffffffffu, rsB, 1);
        rsB += __shfl_xor_sync(0xffffffffu, rsB, 2);
        lrowA = lrowA * aA + rsA;
        lrowB = lrowB * aB + rsB;
#pragma unroll
        for (int nt = 0; nt < 8; nt++) {
            o[nt][0] *= aA; o[nt][1] *= aA;
            o[nt][2] *= aB; o[nt][3] *= aB;
        }

        // ---- stage P (tf32) to warp-private smem in A-frag order
        {
            const int t0  = g * 4 + ((2 * tg) & 3);
            const int rg0 = 2 * (tg >> 1);
#pragma unroll
            for (int nt = 0; nt < 8; nt++) {
                uint32_t p00 = to_tf32(sfr[nt][0]);
                uint32_t p10 = to_tf32(sfr[nt][2]);
                uint32_t p01 = to_tf32(sfr[nt][1]);
                uint32_t p11 = to_tf32(sfr[nt][3]);
                *(uint2*)&Pw[(nt * 32 + t0) * 4 + rg0]     = make_uint2(p00, p10);
                *(uint2*)&Pw[(nt * 32 + t0 + 1) * 4 + rg0] = make_uint2(p01, p11);
            }
        }
        __syncwarp();

        // ---- O += P V (16x64 per warp)
#pragma unroll
        for (int ks = 0; ks < 8; ks++) {
            uint4 av = *(const uint4*)&Pw[(ks * 32 + lane) * 4];
            uint32_t af[4] = {av.x, av.y, av.z, av.w};
#pragma unroll
            for (int nt = 0; nt < 8; nt++) {
                uint2 bv = *(const uint2*)&sVs[((ks * 8 + nt) * 32 + lane) * 2];
                uint32_t bf[2] = {bv.x, bv.y};
                MMA_TF32(o[nt], af, bf);
            }
        }
        __syncwarp();
    }

    // ---- finalize: g_y[b*T+t][h*64+d]
    const int b = bh / HH;
    const int h = bh % HH;
    const float invA = 1.0f / lrowA;
    const float invB = 1.0f / lrowB;
    float* rowA = g_y + (size_t)(b * TT + iA) * CC + h * DH;
    float* rowB = g_y + (size_t)(b * TT + iB) * CC + h * DH;
#pragma unroll
    for (int nt = 0; nt < 8; nt++) {
        int d = nt * 8 + 2 * tg;
        *(float2*)(rowA + d) = make_float2(o[nt][0] * invA, o[nt][1] * invA);
        *(float2*)(rowB + d) = make_float2(o[nt][2] * invB, o[nt][3] * invB);
    }
}

// ---------------------------------------------------------------------------

extern "C" void kernel_launch(void* const* d_in, const int* in_sizes, int n_in,
                              void* d_out, int out_size)
{
    const float* x  = (const float*)d_in[0];
    const float* Wk = (const float*)d_in[1];
    const float* Wq = (const float*)d_in[2];
    const float* Wv = (const float*)d_in[3];
    const float* Wp = (const float*)d_in[4];
    const float* bp = (const float*)d_in[5];
    float* out = (float*)d_out;

    const int attn_smem = 98304;   // 96KB
    cudaFuncSetAttribute(attn_mma_kernel,
                         cudaFuncAttributeMaxDynamicSharedMemorySize, attn_smem);

    // QKV projections (tf32 mma.sync) -> fragment-ordered Q/K/V
    qkv_mma_kernel<<<dim3(6, 64, 3), 256>>>(x, Wq, Wk, Wv);

    // Flash attention, cp.async double-buffered K/V
    attn_mma_kernel<<<dim3(32, 24), 256, attn_smem>>>();

    // Output projection + bias (tf32 mma.sync)
    proj_mma_kernel<<<dim3(6, 64), 256>>>(Wp, bp, out);
}